// round 12
// baseline (speedup 1.0000x reference)
#include <cuda_runtime.h>
#include <cstdint>
#include <math.h>

#define T      1024
#define LRC    0.01f

// Scratch (device globals — allocation is forbidden)
__device__ float g_cw[16 * T];      // control weights [rs, n]
__device__ float g_epart[32];       // 8 cluster ranks x 4 e partials

// ---------------------------------------------------------------------------
// k1 (8-CTA cluster, 256 thr/CTA): fused err + cw + gamma + out zero-init.
// Fires the PDL trigger immediately so k2 can start staging Fx in parallel.
// ---------------------------------------------------------------------------
__global__ void __cluster_dims__(8, 1, 1) k1(const float* __restrict__ Fx,
                                             const float* __restrict__ Dis,
                                             const float* __restrict__ w0,
                                             float* __restrict__ out) {
    asm volatile("griddepcontrol.launch_dependents;");

    const int tid  = threadIdx.x;
    const int rank = blockIdx.x;
    const float4* w4  = (const float4*)w0;
    const float4* fx4 = (const float4*)Fx;

    // ---- phase A: partial err dot products over this CTA's slice ----
    float acc[4] = {0.f, 0.f, 0.f, 0.f};
#pragma unroll
    for (int s = 0; s < 2; s++) {
        const int i4 = rank * 512 + s * 256 + tid;    // float4 index into w0
        const float4 w = w4[i4];
        const int rs = i4 >> 8, n4 = i4 & 255;
#pragma unroll
        for (int e = 0; e < 4; e++) {
            const float4 x = fx4[(rs << 10) + (e << 8) + n4];
            acc[e] += x.x * w.x + x.y * w.y + x.z * w.z + x.w * w.w;
        }
    }
#pragma unroll
    for (int o = 16; o; o >>= 1)
#pragma unroll
        for (int e = 0; e < 4; e++) acc[e] += __shfl_xor_sync(0xffffffffu, acc[e], o);

    __shared__ float sp[8][4];
    __shared__ float serr[4];
    if ((tid & 31) == 0)
#pragma unroll
        for (int e = 0; e < 4; e++) sp[tid >> 5][e] = acc[e];
    __syncthreads();
    if (tid < 4) {
        float s = 0.f;
#pragma unroll
        for (int wq = 0; wq < 8; wq++) s += sp[wq][tid];
        g_epart[rank * 4 + tid] = s;
    }

    asm volatile("barrier.cluster.arrive.release.aligned;" ::: "memory");

    // ---- barrier gap: zero out[0:4096) + gamma vector (independent work) ----
    {
        const int g = rank * 256 + tid;               // 0..2047
        if (g < 1024) {
            ((float4*)out)[g] = make_float4(0.f, 0.f, 0.f, 0.f);
            out[4096 + g] = __expf((float)(1023 - g) * -1.0005003e-3f);
        }
    }

    asm volatile("barrier.cluster.wait.acquire.aligned;" ::: "memory");

    if (tid < 4) {
        volatile const float* gp = g_epart;
        float s = 0.f;
#pragma unroll
        for (int r = 0; r < 8; r++) s += gp[r * 4 + tid];
        serr[tid] = Dis[tid * T + (T - 1)] - s;
    }
    __syncthreads();
    const float e0 = serr[0], e1 = serr[1], e2 = serr[2], e3 = serr[3];

    // ---- phase B: cw over the same slice (Fx/w0 L1-hot) ----
    float4* cw4 = (float4*)g_cw;
#pragma unroll
    for (int s = 0; s < 2; s++) {
        const int i4 = rank * 512 + s * 256 + tid;
        float4 c = w4[i4];
        const int rs = i4 >> 8, n4 = i4 & 255;
        const float4 x0 = fx4[(rs << 10) + (0 << 8) + n4];
        const float4 x1 = fx4[(rs << 10) + (1 << 8) + n4];
        const float4 x2 = fx4[(rs << 10) + (2 << 8) + n4];
        const float4 x3 = fx4[(rs << 10) + (3 << 8) + n4];
        c.x += LRC * (x0.x * e0 + x1.x * e1 + x2.x * e2 + x3.x * e3);
        c.y += LRC * (x0.y * e0 + x1.y * e1 + x2.y * e2 + x3.y * e3);
        c.z += LRC * (x0.z * e0 + x1.z * e1 + x2.z * e2 + x3.z * e3);
        c.w += LRC * (x0.w * e0 + x1.w * e1 + x2.w * e2 + x3.w * e3);
        cw4[i4] = c;
    }
}

// ---------------------------------------------------------------------------
// k2: causal correlation. grid (32 pair-tiles, 4 e, 2 rs-halves) = 256 CTAs,
// block 1024, __launch_bounds__(1024,2) -> 2048 thr/SM = 100% occ, ONE wave.
// Subgroup (512 thr) = 4 rs rows; within it: t-half (th) x 256 chunk slots.
// Low-register tile: acc[8] (8 t's x 4 n). The 4 leftover chunks per
// (sub,th) are a second short pass on threads c<4. Reduction region lives
// AFTER the staging region (no overlay). cw read via __ldg (L2-hot).
// Combine: float atomicAdd, exactly 2 contributors/element -> deterministic.
// ---------------------------------------------------------------------------
#define SFQ   1048            // sF row stride in floats (20 pad + 1024 + 4 tail)
#define NF4   262             // float4 per sF row
#define RED0  8448            // reduction region start (floats)
#define RHALF 8192            // reduction floats per subgroup ([16][256] x 2)

extern __shared__ float smem[];

__device__ __forceinline__ void conv8(const int sub, const int th,
                                      const int t0, const int cc,
                                      const int half, float* red) {
    const int nb = cc << 2;
    const int ab = 16 + t0 + (th << 3) - nb;
    const float4* wG = (const float4*)
        (g_cw + (((half << 3) + (sub << 2)) << 10) + nb);
    const float* fBase = &smem[(sub << 2) * SFQ + ab];

    float acc[8];
#pragma unroll
    for (int j = 0; j < 8; j++) acc[j] = 0.f;

#pragma unroll
    for (int qq = 0; qq < 4; qq++) {
        const float4 w = __ldg(wG + (qq << 8));
        const float4* F4 = (const float4*)(fBase + qq * SFQ);
        float ff[12];
#pragma unroll
        for (int m = 0; m < 3; m++) {
            const float4 v = F4[m];
            ff[4 * m + 0] = v.x; ff[4 * m + 1] = v.y;
            ff[4 * m + 2] = v.z; ff[4 * m + 3] = v.w;
        }
#pragma unroll
        for (int j = 0; j < 8; j++)
            acc[j] += ff[4 + j] * w.x + ff[3 + j] * w.y
                    + ff[2 + j] * w.z + ff[1 + j] * w.w;
    }
#pragma unroll
    for (int j = 0; j < 8; j++)
        red[((th << 3) + j) * 256 + cc] = acc[j];
}

__global__ void __launch_bounds__(1024, 2)
k2(const float* __restrict__ Fx, float* __restrict__ out) {
    const int tid  = threadIdx.x;
    const int b    = blockIdx.x;
    const int e    = blockIdx.y;
    const int half = blockIdx.z;                    // rs-half
    const int sub  = tid >> 9;                      // 4-rs subgroup
    const int stl  = tid & 511;
    const int th   = stl >> 8;                      // t-half of the 16-tile
    const int c    = stl & 255;                     // chunk slot
    const int t0A  = b << 4, t0B = (63 - b) << 4;
    const int cA   = (b + 1) << 2;                  // 4..256 chunks, tile A
    const int cB   = 260 - cA;                      // 4..256 chunks, tile B

    const float4 z4 = make_float4(0.f, 0.f, 0.f, 0.f);

    // ---- stage this half's 8 Fx rows (front zero-padded) — k1-independent ----
    float4* dF = (float4*)smem;
    for (int idx = tid; idx < 8 * NF4; idx += 1024) {
        const int qq = idx / NF4, i = idx - qq * NF4;
        float4 v = z4;
        if (i >= 5 && i < 261)
            v = ((const float4*)Fx)[(((((half << 3) + qq) << 2) + e) << 8) + i - 5];
        dF[qq * NF4 + i] = v;
    }
    __syncthreads();

    // ---- wait for k1 (g_cw + out zero-init), then compute directly ----
    asm volatile("griddepcontrol.wait;" ::: "memory");

    float* redA = smem + RED0 + sub * RHALF;        // [16][256]
    float* redB = redA + 4096;                      // [16][256]

    // ---- pass 1: every thread owns one chunk ----
    {
        const bool isA = (c < cA);
        const int t0 = isA ? t0A : t0B;
        const int cc = isA ? c : (c - cA);
        conv8(sub, th, t0, cc, half, isA ? redA : redB);
    }
    // ---- pass 2: leftover 4 tile-B chunks per (sub, th) ----
    if (c < 4)
        conv8(sub, th, t0B, (256 - cA) + c, half, redB);
    __syncthreads();

    // ---- reduce: 32 rows x 32 lanes, full-warp shuffle ----
    {
        const int row = tid >> 5, k = tid & 31;
        float s = 0.f;
        if (row < 16) {
            for (int c2 = k; c2 < cA; c2 += 32)
                s += smem[RED0 + row * 256 + c2]
                   + smem[RED0 + RHALF + row * 256 + c2];
        } else {
            const int r2 = row - 16;
            for (int c2 = k; c2 < cB; c2 += 32)
                s += smem[RED0 + 4096 + r2 * 256 + c2]
                   + smem[RED0 + RHALF + 4096 + r2 * 256 + c2];
        }
#pragma unroll
        for (int o = 16; o; o >>= 1) s += __shfl_xor_sync(0xffffffffu, s, o);

        if (k == 0) {
            const int t = (row < 16) ? (t0A + row) : (t0B + row - 16);
            atomicAdd(&out[(t << 2) + e], s);   // 2 contributors: deterministic
        }
    }
}

// ---------------------------------------------------------------------------
extern "C" void kernel_launch(void* const* d_in, const int* in_sizes, int n_in,
                              void* d_out, int out_size) {
    const float* Fx  = (const float*)d_in[0];   // [4,4,4,1024]
    const float* Dis = (const float*)d_in[1];   // [4,1024]
    const float* w0  = (const float*)d_in[2];   // [4,4,1024]
    float* out = (float*)d_out;                 // [1024*4 anti | 1024 gamma]

    const size_t dynBytes = (size_t)(RED0 + 2 * RHALF) * sizeof(float); // 99,328
    cudaFuncSetAttribute(k2, cudaFuncAttributeMaxDynamicSharedMemorySize,
                         (int)dynBytes);

    k1<<<8, 256>>>(Fx, Dis, w0, out);

    // k2 with programmatic dependent launch (overlaps with k1)
    cudaLaunchConfig_t cfg = {};
    cfg.gridDim = dim3(32, 4, 2);
    cfg.blockDim = dim3(1024);
    cfg.dynamicSmemBytes = dynBytes;
    cfg.stream = 0;
    cudaLaunchAttribute attr[1];
    attr[0].id = cudaLaunchAttributeProgrammaticStreamSerialization;
    attr[0].val.programmaticStreamSerializationAllowed = 1;
    cfg.attrs = attr;
    cfg.numAttrs = 1;
    cudaLaunchKernelEx(&cfg, k2, Fx, out);
}